// round 2
// baseline (speedup 1.0000x reference)
#include <cuda_runtime.h>

// ---------------------------------------------------------------------------
// getMetric: DOA localization metrics (ACC + MAE[ele, azi, aziele])
//
// R2: one item per thread (no grid-stride loop) -> 6 independent LDG.128
// front-batched per thread, 4096 blocks for full-chip load queue depth.
// __ldcs streaming loads (read-once data, skip L2 retention).
// ---------------------------------------------------------------------------

#define DEG2RAD 0.017453292519943295f
#define RAD2DEG 57.295779513082323f
#define VAD_TH  (2.0f / 3.0f)
#define AE_TH   30.0f
#define CLIPV   0.99999f

__device__ float        g_sums[5];   // act, corr, ele, azi, aziele (zero-init at load)
__device__ unsigned int g_done;      // ticket counter (zero-init at load)

// Abramowitz & Stegun 4.4.47 polynomial acos, |err| <= ~2e-8 rad.
__device__ __forceinline__ float fast_acos(float x) {
    float ax = fabsf(x);
    float p = -0.0012624911f;
    p = fmaf(p, ax,  0.0066700901f);
    p = fmaf(p, ax, -0.0170881256f);
    p = fmaf(p, ax,  0.0308918810f);
    p = fmaf(p, ax, -0.0501743046f);
    p = fmaf(p, ax,  0.0889789874f);
    p = fmaf(p, ax, -0.2145988016f);
    p = fmaf(p, ax,  1.5707963050f);
    float r = p * sqrtf(1.0f - ax);
    return (x < 0.0f) ? (3.14159265358979f - r) : r;
}

__device__ __forceinline__ void proc_one(
    float elg, float azg, float ele_, float aze, float vg, float ve,
    float& s_act, float& s_corr, float& s_ele, float& s_azi, float& s_ae)
{
    float vgf = (vg > VAD_TH) ? 1.0f : 0.0f;
    float vef = (ve > VAD_TH) ? vgf : 0.0f;

    // azimuth error: |mod(est - gt + 180, 360) - 180|
    float d = aze - azg;                        // (-360, 360)
    float r = d + 180.0f;                       // (-180, 540)
    r -= 360.0f * floorf(r * (1.0f / 360.0f));  // [0, 360)
    float azi_err = fabsf(r - 180.0f);

    float ele_err = fabsf(ele_ - elg);

    // great-circle angular error
    float sg, cg, se, ce;
    __sincosf(elg  * DEG2RAD, &sg, &cg);
    __sincosf(ele_ * DEG2RAD, &se, &ce);
    float cda = __cosf(d * DEG2RAD);
    float aux = fmaf(cg, ce, sg * se * cda);
    aux = fminf(fmaxf(aux, -CLIPV), CLIPV);
    float ae_deg = fast_acos(aux) * RAD2DEG;

    s_act  += vgf;
    s_corr += (azi_err < AE_TH) ? vef : 0.0f;
    s_ele   = fmaf(vgf, ele_err,  s_ele);
    s_azi   = fmaf(vgf, azi_err,  s_azi);
    s_ae    = fmaf(vgf, ae_deg,   s_ae);
}

__global__ void __launch_bounds__(256)
getMetric_kernel(const float4* __restrict__ doa_gt,
                 const float4* __restrict__ vad_gt,
                 const float4* __restrict__ doa_est,
                 const float4* __restrict__ vad_est,
                 float* __restrict__ out,
                 int n_items)
{
    float s_act = 0.f, s_corr = 0.f, s_ele = 0.f, s_azi = 0.f, s_ae = 0.f;

    const int i = blockIdx.x * blockDim.x + threadIdx.x;
    if (i < n_items) {
        // 6 independent streaming loads, all issued before any consumption
        float4 eg = __ldcs(&doa_gt [2 * i]);
        float4 ag = __ldcs(&doa_gt [2 * i + 1]);
        float4 ee = __ldcs(&doa_est[2 * i]);
        float4 ae = __ldcs(&doa_est[2 * i + 1]);
        float4 vg = __ldcs(&vad_gt [i]);
        float4 ve = __ldcs(&vad_est[i]);

        proc_one(eg.x, ag.x, ee.x, ae.x, vg.x, ve.x, s_act, s_corr, s_ele, s_azi, s_ae);
        proc_one(eg.y, ag.y, ee.y, ae.y, vg.y, ve.y, s_act, s_corr, s_ele, s_azi, s_ae);
        proc_one(eg.z, ag.z, ee.z, ae.z, vg.z, ve.z, s_act, s_corr, s_ele, s_azi, s_ae);
        proc_one(eg.w, ag.w, ee.w, ae.w, vg.w, ve.w, s_act, s_corr, s_ele, s_azi, s_ae);
    }

    // ---- warp reduction ----
    #pragma unroll
    for (int o = 16; o > 0; o >>= 1) {
        s_act  += __shfl_xor_sync(0xFFFFFFFFu, s_act,  o);
        s_corr += __shfl_xor_sync(0xFFFFFFFFu, s_corr, o);
        s_ele  += __shfl_xor_sync(0xFFFFFFFFu, s_ele,  o);
        s_azi  += __shfl_xor_sync(0xFFFFFFFFu, s_azi,  o);
        s_ae   += __shfl_xor_sync(0xFFFFFFFFu, s_ae,   o);
    }

    // ---- block reduction (8 warps @ 256 threads) ----
    __shared__ float smem[5][8];
    const int lane = threadIdx.x & 31;
    const int wid  = threadIdx.x >> 5;
    if (lane == 0) {
        smem[0][wid] = s_act; smem[1][wid] = s_corr; smem[2][wid] = s_ele;
        smem[3][wid] = s_azi; smem[4][wid] = s_ae;
    }
    __syncthreads();

    if (threadIdx.x == 0) {
        float b[5];
        #pragma unroll
        for (int k = 0; k < 5; k++) {
            float v = smem[k][0];
            #pragma unroll
            for (int w = 1; w < 8; w++) v += smem[k][w];
            b[k] = v;
        }
        #pragma unroll
        for (int k = 0; k < 5; k++) atomicAdd(&g_sums[k], b[k]);

        __threadfence();
        unsigned int ticket = atomicAdd(&g_done, 1u);
        if (ticket == gridDim.x - 1) {
            float act   = atomicAdd(&g_sums[0], 0.0f);
            float corr  = atomicAdd(&g_sums[1], 0.0f);
            float ele   = atomicAdd(&g_sums[2], 0.0f);
            float azi   = atomicAdd(&g_sums[3], 0.0f);
            float aziel = atomicAdd(&g_sums[4], 0.0f);

            float inv = 1.0f / act;
            out[0] = corr  * inv;   // ACC
            out[1] = ele   * inv;   // MAE ele
            out[2] = azi   * inv;   // MAE azi
            out[3] = aziel * inv;   // MAE aziele

            // self-reset for next graph replay
            #pragma unroll
            for (int k = 0; k < 5; k++) atomicExch(&g_sums[k], 0.0f);
            atomicExch(&g_done, 0u);
        }
    }
}

extern "C" void kernel_launch(void* const* d_in, const int* in_sizes, int n_in,
                              void* d_out, int out_size)
{
    const float4* doa_gt  = (const float4*)d_in[0];
    const float4* vad_gt  = (const float4*)d_in[1];
    const float4* doa_est = (const float4*)d_in[2];
    const float4* vad_est = (const float4*)d_in[3];
    float* out = (float*)d_out;

    const int n_items = in_sizes[1] / 4;   // nb*nt  (vad has ns=4 per item)

    const int threads = 256;
    const int blocks  = (n_items + threads - 1) / threads;   // one item per thread
    getMetric_kernel<<<blocks, threads>>>(doa_gt, vad_gt, doa_est, vad_est,
                                          out, n_items);
}

// round 3
// speedup vs baseline: 2.1333x; 2.1333x over previous
#include <cuda_runtime.h>

// ---------------------------------------------------------------------------
// getMetric: DOA localization metrics (ACC + MAE[ele, azi, aziele])
//
// R3: R1 grid-stride base (1024 x 256, 4 iters/thread) + depth-2 software
// pipeline (next iteration's 6 LDG.128 issued before current compute,
// steady-state MLP 12/thread) + trig-identity great-circle formula
// (3 cos + sqrt instead of 2 sincos + cos + sqrt -> MUFU 6->4 per source).
// ---------------------------------------------------------------------------

#define DEG2RAD 0.017453292519943295f
#define RAD2DEG 57.295779513082323f
#define VAD_TH  (2.0f / 3.0f)
#define AE_TH   30.0f
#define CLIPV   0.99999f

__device__ float        g_sums[5];   // act, corr, ele, azi, aziele (zero-init at load)
__device__ unsigned int g_done;      // ticket counter (zero-init at load)

// Abramowitz & Stegun 4.4.47 polynomial acos, |err| <= ~2e-8 rad.
__device__ __forceinline__ float fast_acos(float x) {
    float ax = fabsf(x);
    float p = -0.0012624911f;
    p = fmaf(p, ax,  0.0066700901f);
    p = fmaf(p, ax, -0.0170881256f);
    p = fmaf(p, ax,  0.0308918810f);
    p = fmaf(p, ax, -0.0501743046f);
    p = fmaf(p, ax,  0.0889789874f);
    p = fmaf(p, ax, -0.2145988016f);
    p = fmaf(p, ax,  1.5707963050f);
    float r = p * sqrtf(1.0f - ax);
    return (x < 0.0f) ? (3.14159265358979f - r) : r;
}

struct Item { float4 eg, ag, ee, ae, vg, ve; };

__device__ __forceinline__ Item load_item(
    const float4* __restrict__ doa_gt, const float4* __restrict__ vad_gt,
    const float4* __restrict__ doa_est, const float4* __restrict__ vad_est,
    int i)
{
    Item it;
    it.eg = doa_gt [2 * i];
    it.ag = doa_gt [2 * i + 1];
    it.ee = doa_est[2 * i];
    it.ae = doa_est[2 * i + 1];
    it.vg = vad_gt [i];
    it.ve = vad_est[i];
    return it;
}

__device__ __forceinline__ void proc_one(
    float elg, float azg, float ele_, float aze, float vg, float ve,
    float& s_act, float& s_corr, float& s_ele, float& s_azi, float& s_ae)
{
    float vgf = (vg > VAD_TH) ? 1.0f : 0.0f;
    float vef = (ve > VAD_TH) ? vgf : 0.0f;

    // azimuth error: |mod(est - gt + 180, 360) - 180|
    float d = aze - azg;                        // (-360, 360)
    float r = d + 180.0f;                       // (-180, 540)
    r -= 360.0f * floorf(r * (1.0f / 360.0f));  // [0, 360)
    float azi_err = fabsf(r - 180.0f);

    float dele = ele_ - elg;
    float ele_err = fabsf(dele);

    // great-circle error via product-to-sum:
    //   cos(a)cos(b) + sin(a)sin(b)cos(c)
    // = 0.5*[cos(a-b)*(1+cos(c)) + cos(a+b)*(1-cos(c))]
    float cde = __cosf(dele * DEG2RAD);          // cos(ele_gt - ele_es)
    float cse = __cosf((ele_ + elg) * DEG2RAD);  // cos(ele_gt + ele_es)
    float cda = __cosf(d * DEG2RAD);             // cos(azi_gt - azi_es)
    float aux = 0.5f * fmaf(cde, 1.0f + cda, cse * (1.0f - cda));
    aux = fminf(fmaxf(aux, -CLIPV), CLIPV);
    float ae_deg = fast_acos(aux) * RAD2DEG;

    s_act  += vgf;
    s_corr += (azi_err < AE_TH) ? vef : 0.0f;
    s_ele   = fmaf(vgf, ele_err,  s_ele);
    s_azi   = fmaf(vgf, azi_err,  s_azi);
    s_ae    = fmaf(vgf, ae_deg,   s_ae);
}

__device__ __forceinline__ void proc_item(
    const Item& it,
    float& s_act, float& s_corr, float& s_ele, float& s_azi, float& s_ae)
{
    proc_one(it.eg.x, it.ag.x, it.ee.x, it.ae.x, it.vg.x, it.ve.x, s_act, s_corr, s_ele, s_azi, s_ae);
    proc_one(it.eg.y, it.ag.y, it.ee.y, it.ae.y, it.vg.y, it.ve.y, s_act, s_corr, s_ele, s_azi, s_ae);
    proc_one(it.eg.z, it.ag.z, it.ee.z, it.ae.z, it.vg.z, it.ve.z, s_act, s_corr, s_ele, s_azi, s_ae);
    proc_one(it.eg.w, it.ag.w, it.ee.w, it.ae.w, it.vg.w, it.ve.w, s_act, s_corr, s_ele, s_azi, s_ae);
}

__global__ void __launch_bounds__(256)
getMetric_kernel(const float4* __restrict__ doa_gt,
                 const float4* __restrict__ vad_gt,
                 const float4* __restrict__ doa_est,
                 const float4* __restrict__ vad_est,
                 float* __restrict__ out,
                 int n_items)
{
    float s_act = 0.f, s_corr = 0.f, s_ele = 0.f, s_azi = 0.f, s_ae = 0.f;

    const int stride = gridDim.x * blockDim.x;
    int i = blockIdx.x * blockDim.x + threadIdx.x;

    if (i < n_items) {
        Item cur = load_item(doa_gt, vad_gt, doa_est, vad_est, i);
        for (;;) {
            const int j = i + stride;
            const bool more = (j < n_items);
            Item nxt;
            if (more)
                nxt = load_item(doa_gt, vad_gt, doa_est, vad_est, j);  // prefetch
            proc_item(cur, s_act, s_corr, s_ele, s_azi, s_ae);
            if (!more) break;
            cur = nxt;
            i = j;
        }
    }

    // ---- warp reduction ----
    #pragma unroll
    for (int o = 16; o > 0; o >>= 1) {
        s_act  += __shfl_xor_sync(0xFFFFFFFFu, s_act,  o);
        s_corr += __shfl_xor_sync(0xFFFFFFFFu, s_corr, o);
        s_ele  += __shfl_xor_sync(0xFFFFFFFFu, s_ele,  o);
        s_azi  += __shfl_xor_sync(0xFFFFFFFFu, s_azi,  o);
        s_ae   += __shfl_xor_sync(0xFFFFFFFFu, s_ae,   o);
    }

    // ---- block reduction (8 warps @ 256 threads) ----
    __shared__ float smem[5][8];
    const int lane = threadIdx.x & 31;
    const int wid  = threadIdx.x >> 5;
    if (lane == 0) {
        smem[0][wid] = s_act; smem[1][wid] = s_corr; smem[2][wid] = s_ele;
        smem[3][wid] = s_azi; smem[4][wid] = s_ae;
    }
    __syncthreads();

    if (threadIdx.x == 0) {
        float b[5];
        #pragma unroll
        for (int k = 0; k < 5; k++) {
            float v = smem[k][0];
            #pragma unroll
            for (int w = 1; w < 8; w++) v += smem[k][w];
            b[k] = v;
        }
        #pragma unroll
        for (int k = 0; k < 5; k++) atomicAdd(&g_sums[k], b[k]);

        __threadfence();
        unsigned int ticket = atomicAdd(&g_done, 1u);
        if (ticket == gridDim.x - 1) {
            float act   = atomicAdd(&g_sums[0], 0.0f);
            float corr  = atomicAdd(&g_sums[1], 0.0f);
            float ele   = atomicAdd(&g_sums[2], 0.0f);
            float azi   = atomicAdd(&g_sums[3], 0.0f);
            float aziel = atomicAdd(&g_sums[4], 0.0f);

            float inv = 1.0f / act;
            out[0] = corr  * inv;   // ACC
            out[1] = ele   * inv;   // MAE ele
            out[2] = azi   * inv;   // MAE azi
            out[3] = aziel * inv;   // MAE aziele

            // self-reset for next graph replay
            #pragma unroll
            for (int k = 0; k < 5; k++) atomicExch(&g_sums[k], 0.0f);
            atomicExch(&g_done, 0u);
        }
    }
}

extern "C" void kernel_launch(void* const* d_in, const int* in_sizes, int n_in,
                              void* d_out, int out_size)
{
    const float4* doa_gt  = (const float4*)d_in[0];
    const float4* vad_gt  = (const float4*)d_in[1];
    const float4* doa_est = (const float4*)d_in[2];
    const float4* vad_est = (const float4*)d_in[3];
    float* out = (float*)d_out;

    const int n_items = in_sizes[1] / 4;   // nb*nt  (vad has ns=4 per item)

    const int threads = 256;
    const int blocks  = 1024;              // 262144 threads -> 4 items/thread
    getMetric_kernel<<<blocks, threads>>>(doa_gt, vad_gt, doa_est, vad_est,
                                          out, n_items);
}

// round 4
// speedup vs baseline: 2.4242x; 1.1364x over previous
#include <cuda_runtime.h>

// ---------------------------------------------------------------------------
// getMetric: DOA localization metrics (ACC + MAE[ele, azi, aziele])
//
// R4: R3 pipelined grid-stride kernel, but grid = 148 SMs x 4 CTAs/SM = 592
// (exactly one resident wave at the 64-reg occupancy limit). Eliminates the
// 1.73-wave quantization of R3 (grid=1024, occ cap 592): no half-empty wave,
// steady-state MLP-12 for the whole kernel. ~7 iterations/thread.
// ---------------------------------------------------------------------------

#define DEG2RAD 0.017453292519943295f
#define RAD2DEG 57.295779513082323f
#define VAD_TH  (2.0f / 3.0f)
#define AE_TH   30.0f
#define CLIPV   0.99999f

#define NUM_SMS 148
#define CTAS_PER_SM 4

__device__ float        g_sums[5];   // act, corr, ele, azi, aziele (zero-init at load)
__device__ unsigned int g_done;      // ticket counter (zero-init at load)

// Abramowitz & Stegun 4.4.47 polynomial acos, |err| <= ~2e-8 rad.
__device__ __forceinline__ float fast_acos(float x) {
    float ax = fabsf(x);
    float p = -0.0012624911f;
    p = fmaf(p, ax,  0.0066700901f);
    p = fmaf(p, ax, -0.0170881256f);
    p = fmaf(p, ax,  0.0308918810f);
    p = fmaf(p, ax, -0.0501743046f);
    p = fmaf(p, ax,  0.0889789874f);
    p = fmaf(p, ax, -0.2145988016f);
    p = fmaf(p, ax,  1.5707963050f);
    float r = p * sqrtf(1.0f - ax);
    return (x < 0.0f) ? (3.14159265358979f - r) : r;
}

struct Item { float4 eg, ag, ee, ae, vg, ve; };

__device__ __forceinline__ Item load_item(
    const float4* __restrict__ doa_gt, const float4* __restrict__ vad_gt,
    const float4* __restrict__ doa_est, const float4* __restrict__ vad_est,
    int i)
{
    Item it;
    it.eg = doa_gt [2 * i];
    it.ag = doa_gt [2 * i + 1];
    it.ee = doa_est[2 * i];
    it.ae = doa_est[2 * i + 1];
    it.vg = vad_gt [i];
    it.ve = vad_est[i];
    return it;
}

__device__ __forceinline__ void proc_one(
    float elg, float azg, float ele_, float aze, float vg, float ve,
    float& s_act, float& s_corr, float& s_ele, float& s_azi, float& s_ae)
{
    float vgf = (vg > VAD_TH) ? 1.0f : 0.0f;
    float vef = (ve > VAD_TH) ? vgf : 0.0f;

    // azimuth error: |mod(est - gt + 180, 360) - 180|
    float d = aze - azg;                        // (-360, 360)
    float r = d + 180.0f;                       // (-180, 540)
    r -= 360.0f * floorf(r * (1.0f / 360.0f));  // [0, 360)
    float azi_err = fabsf(r - 180.0f);

    float dele = ele_ - elg;
    float ele_err = fabsf(dele);

    // great-circle error via product-to-sum:
    //   cos(a)cos(b) + sin(a)sin(b)cos(c)
    // = 0.5*[cos(a-b)*(1+cos(c)) + cos(a+b)*(1-cos(c))]
    float cde = __cosf(dele * DEG2RAD);          // cos(ele_gt - ele_es)
    float cse = __cosf((ele_ + elg) * DEG2RAD);  // cos(ele_gt + ele_es)
    float cda = __cosf(d * DEG2RAD);             // cos(azi_gt - azi_es)
    float aux = 0.5f * fmaf(cde, 1.0f + cda, cse * (1.0f - cda));
    aux = fminf(fmaxf(aux, -CLIPV), CLIPV);
    float ae_deg = fast_acos(aux) * RAD2DEG;

    s_act  += vgf;
    s_corr += (azi_err < AE_TH) ? vef : 0.0f;
    s_ele   = fmaf(vgf, ele_err,  s_ele);
    s_azi   = fmaf(vgf, azi_err,  s_azi);
    s_ae    = fmaf(vgf, ae_deg,   s_ae);
}

__device__ __forceinline__ void proc_item(
    const Item& it,
    float& s_act, float& s_corr, float& s_ele, float& s_azi, float& s_ae)
{
    proc_one(it.eg.x, it.ag.x, it.ee.x, it.ae.x, it.vg.x, it.ve.x, s_act, s_corr, s_ele, s_azi, s_ae);
    proc_one(it.eg.y, it.ag.y, it.ee.y, it.ae.y, it.vg.y, it.ve.y, s_act, s_corr, s_ele, s_azi, s_ae);
    proc_one(it.eg.z, it.ag.z, it.ee.z, it.ae.z, it.vg.z, it.ve.z, s_act, s_corr, s_ele, s_azi, s_ae);
    proc_one(it.eg.w, it.ag.w, it.ee.w, it.ae.w, it.vg.w, it.ve.w, s_act, s_corr, s_ele, s_azi, s_ae);
}

__global__ void __launch_bounds__(256, CTAS_PER_SM)
getMetric_kernel(const float4* __restrict__ doa_gt,
                 const float4* __restrict__ vad_gt,
                 const float4* __restrict__ doa_est,
                 const float4* __restrict__ vad_est,
                 float* __restrict__ out,
                 int n_items)
{
    float s_act = 0.f, s_corr = 0.f, s_ele = 0.f, s_azi = 0.f, s_ae = 0.f;

    const int stride = gridDim.x * blockDim.x;
    int i = blockIdx.x * blockDim.x + threadIdx.x;

    if (i < n_items) {
        Item cur = load_item(doa_gt, vad_gt, doa_est, vad_est, i);
        for (;;) {
            const int j = i + stride;
            const bool more = (j < n_items);
            Item nxt;
            if (more)
                nxt = load_item(doa_gt, vad_gt, doa_est, vad_est, j);  // prefetch
            proc_item(cur, s_act, s_corr, s_ele, s_azi, s_ae);
            if (!more) break;
            cur = nxt;
            i = j;
        }
    }

    // ---- warp reduction ----
    #pragma unroll
    for (int o = 16; o > 0; o >>= 1) {
        s_act  += __shfl_xor_sync(0xFFFFFFFFu, s_act,  o);
        s_corr += __shfl_xor_sync(0xFFFFFFFFu, s_corr, o);
        s_ele  += __shfl_xor_sync(0xFFFFFFFFu, s_ele,  o);
        s_azi  += __shfl_xor_sync(0xFFFFFFFFu, s_azi,  o);
        s_ae   += __shfl_xor_sync(0xFFFFFFFFu, s_ae,   o);
    }

    // ---- block reduction (8 warps @ 256 threads) ----
    __shared__ float smem[5][8];
    const int lane = threadIdx.x & 31;
    const int wid  = threadIdx.x >> 5;
    if (lane == 0) {
        smem[0][wid] = s_act; smem[1][wid] = s_corr; smem[2][wid] = s_ele;
        smem[3][wid] = s_azi; smem[4][wid] = s_ae;
    }
    __syncthreads();

    if (threadIdx.x == 0) {
        float b[5];
        #pragma unroll
        for (int k = 0; k < 5; k++) {
            float v = smem[k][0];
            #pragma unroll
            for (int w = 1; w < 8; w++) v += smem[k][w];
            b[k] = v;
        }
        #pragma unroll
        for (int k = 0; k < 5; k++) atomicAdd(&g_sums[k], b[k]);

        __threadfence();
        unsigned int ticket = atomicAdd(&g_done, 1u);
        if (ticket == gridDim.x - 1) {
            float act   = atomicAdd(&g_sums[0], 0.0f);
            float corr  = atomicAdd(&g_sums[1], 0.0f);
            float ele   = atomicAdd(&g_sums[2], 0.0f);
            float azi   = atomicAdd(&g_sums[3], 0.0f);
            float aziel = atomicAdd(&g_sums[4], 0.0f);

            float inv = 1.0f / act;
            out[0] = corr  * inv;   // ACC
            out[1] = ele   * inv;   // MAE ele
            out[2] = azi   * inv;   // MAE azi
            out[3] = aziel * inv;   // MAE aziele

            // self-reset for next graph replay
            #pragma unroll
            for (int k = 0; k < 5; k++) atomicExch(&g_sums[k], 0.0f);
            atomicExch(&g_done, 0u);
        }
    }
}

extern "C" void kernel_launch(void* const* d_in, const int* in_sizes, int n_in,
                              void* d_out, int out_size)
{
    const float4* doa_gt  = (const float4*)d_in[0];
    const float4* vad_gt  = (const float4*)d_in[1];
    const float4* doa_est = (const float4*)d_in[2];
    const float4* vad_est = (const float4*)d_in[3];
    float* out = (float*)d_out;

    const int n_items = in_sizes[1] / 4;   // nb*nt  (vad has ns=4 per item)

    const int threads = 256;
    const int blocks  = NUM_SMS * CTAS_PER_SM;   // exactly one resident wave
    getMetric_kernel<<<blocks, threads>>>(doa_gt, vad_gt, doa_est, vad_est,
                                          out, n_items);
}